// round 1
// baseline (speedup 1.0000x reference)
#include <cuda_runtime.h>

#define Bn   64
#define Sn   1024
#define Dn   1024
#define NT   34      // num tags incl BOS
#define BOSI 33

// -------- scratch (static device allocations; no cudaMalloc) --------
__device__ float g_proj_t[(size_t)Bn * NT * Sn];   // [b][j][t] transposed projection
__device__ float g_partition[Bn];
__device__ float g_score[Bn];

// ============================ GEMM ============================
// proj = emissions @ W + b.  M=65536 rows, K=1024, N=34.
// Block: 128 threads, 256 rows (2 rows/thread), 34(->36 padded) cols/thread.
#define KT            32
#define GEMM_THREADS  128
#define ROWS_PER_BLK  256

#define GEMM_U(EA0, EA1, KK) do{                                          \
    const float4* wr_ = (const float4*)(&Wt[(KK)][0]);                    \
    _Pragma("unroll")                                                     \
    for (int j4 = 0; j4 < 9; j4++){                                       \
        float4 w_ = wr_[j4];                                              \
        acc0[j4*4+0] += (EA0)*w_.x; acc0[j4*4+1] += (EA0)*w_.y;           \
        acc0[j4*4+2] += (EA0)*w_.z; acc0[j4*4+3] += (EA0)*w_.w;           \
        acc1[j4*4+0] += (EA1)*w_.x; acc1[j4*4+1] += (EA1)*w_.y;           \
        acc1[j4*4+2] += (EA1)*w_.z; acc1[j4*4+3] += (EA1)*w_.w;           \
    }                                                                     \
} while(0)

__global__ __launch_bounds__(GEMM_THREADS)
void gemm_kernel(const float* __restrict__ em, const float* __restrict__ W,
                 const float* __restrict__ bias, float* __restrict__ out)
{
    __shared__ __align__(16) float Wt[KT][36];
    int tid  = threadIdx.x;
    int row0 = blockIdx.x * ROWS_PER_BLK + tid;
    int row1 = row0 + GEMM_THREADS;

    float acc0[36], acc1[36];
    #pragma unroll
    for (int j = 0; j < 36; j++){ acc0[j] = 0.f; acc1[j] = 0.f; }

    const float4* e0 = (const float4*)(em + (size_t)row0 * Dn);
    const float4* e1 = (const float4*)(em + (size_t)row1 * Dn);

    for (int k0 = 0; k0 < Dn; k0 += KT){
        __syncthreads();
        for (int i = tid; i < KT*36; i += GEMM_THREADS){
            int kk = i / 36, j = i - kk*36;
            Wt[kk][j] = (j < NT) ? W[(size_t)(k0 + kk)*NT + j] : 0.f;
        }
        __syncthreads();

        int kb4 = k0 >> 2;
        #pragma unroll
        for (int kk4 = 0; kk4 < KT/4; kk4++){
            float4 a0 = e0[kb4 + kk4];
            float4 a1 = e1[kb4 + kk4];
            const int kk = kk4*4;
            GEMM_U(a0.x, a1.x, kk+0);
            GEMM_U(a0.y, a1.y, kk+1);
            GEMM_U(a0.z, a1.z, kk+2);
            GEMM_U(a0.w, a1.w, kk+3);
        }
    }

    int b0 = row0 >> 10, s0 = row0 & 1023;
    int b1 = row1 >> 10, s1 = row1 & 1023;
    #pragma unroll
    for (int j = 0; j < NT; j++){
        float bj = bias[j];
        float v0 = acc0[j] + bj;
        float v1 = acc1[j] + bj;
        g_proj_t[((size_t)b0*NT + j)*Sn + s0] = v0;
        g_proj_t[((size_t)b1*NT + j)*Sn + s1] = v1;
        if (j < NT-1){
            out[1 + (size_t)row0*(NT-1) + j] = v0;
            out[1 + (size_t)row1*(NT-1) + j] = v1;
        }
    }
}

// ============================ CRF forward scan ============================
// One block (64 threads) per batch. Thread j owns state j (j<34).
// alpha_{t}[j] = em_t[j] + log sum_i exp(alpha_{t-1}[i]) * E[i][j], shifted by alpha[0].
// E[:,j] lives in registers; p (=exp(alpha-shift)) is broadcast through smem.

#define CRF_STEP(EM, MK) do {                                              \
    __syncthreads();                                                       \
    if (act) {                                                             \
        const float4* p4_ = (const float4*)p_sh;                           \
        float mv0=0.f, mv1=0.f, mv2=0.f, mv3=0.f;                          \
        _Pragma("unroll")                                                  \
        for (int i4 = 0; i4 < 9; i4++){                                    \
            float4 pv_ = p4_[i4];                                          \
            mv0 += pv_.x * Ereg[i4*4+0];                                   \
            mv1 += pv_.y * Ereg[i4*4+1];                                   \
            mv2 += pv_.z * Ereg[i4*4+2];                                   \
            mv3 += pv_.w * Ereg[i4*4+3];                                   \
        }                                                                  \
        float mv_ = (mv0+mv1) + (mv2+mv3);                                 \
        float na_ = (EM) + shift + __logf(fmaxf(mv_, 1e-30f));             \
        alpha = (MK)*na_ + (1.f-(MK))*alpha;                               \
    }                                                                      \
    na_sh[j] = alpha;                                                      \
    __syncthreads();                                                       \
    shift = na_sh[0];                                                      \
    if (act) p_sh[j] = __expf(alpha - shift);                              \
} while(0)

__global__ __launch_bounds__(64)
void scan_kernel(const float* __restrict__ T, const float* __restrict__ mask)
{
    __shared__ __align__(16) float p_sh[40];
    __shared__ float na_sh[64];

    int b = blockIdx.x;
    int j = threadIdx.x;
    bool act = (j < NT);

    float Ereg[36];
    if (act){
        #pragma unroll
        for (int i = 0; i < NT; i++) Ereg[i] = __expf(T[i*NT + j]);
        Ereg[34] = 0.f; Ereg[35] = 0.f;
    } else {
        #pragma unroll
        for (int i = 0; i < 36; i++) Ereg[i] = 0.f;
    }

    const float*  emp  = g_proj_t + ((size_t)b*NT + (act ? j : 0)) * Sn;
    const float4* emp4 = (const float4*)emp;
    const float4* mp4  = (const float4*)(mask + (size_t)b * Sn);

    float alpha = -1e30f;
    if (act) alpha = T[BOSI*NT + j] + emp[0];
    na_sh[j] = alpha;
    if (j == NT) { p_sh[34] = 0.f; p_sh[35] = 0.f; }
    __syncthreads();
    float shift = na_sh[0];
    if (act) p_sh[j] = __expf(alpha - shift);

    float4 emv = emp4[0];
    float4 mkv = mp4[0];
    float4 emn = emp4[1];
    float4 mkn = mp4[1];

    // t = 1..3
    CRF_STEP(emv.y, mkv.y);
    CRF_STEP(emv.z, mkv.z);
    CRF_STEP(emv.w, mkv.w);

    for (int g = 1; g < Sn/4; g++){
        emv = emn; mkv = mkn;
        if (g + 1 < Sn/4){ emn = emp4[g+1]; mkn = mp4[g+1]; }
        CRF_STEP(emv.x, mkv.x);
        CRF_STEP(emv.y, mkv.y);
        CRF_STEP(emv.z, mkv.z);
        CRF_STEP(emv.w, mkv.w);
    }

    // partition = logsumexp over final alphas (na_sh holds them, synced)
    if (j == 0){
        float m = -1e30f;
        #pragma unroll
        for (int i = 0; i < NT; i++) m = fmaxf(m, na_sh[i]);
        float ss = 0.f;
        #pragma unroll
        for (int i = 0; i < NT; i++) ss += __expf(na_sh[i] - m);
        g_partition[b] = m + __logf(ss);
    }
}

// ============================ gold-path score ============================
__global__ __launch_bounds__(32)
void score_kernel(const int* __restrict__ tags, const float* __restrict__ mask,
                  const float* __restrict__ T)
{
    int b = blockIdx.x, lane = threadIdx.x;
    float partial = 0.f;
    for (int t = lane; t < Sn; t += 32){
        int   tg = tags[b*Sn + t];
        float e  = g_proj_t[((size_t)b*NT + tg)*Sn + t];
        if (t == 0){
            partial += T[BOSI*NT + tg] + e;
        } else {
            int tgp = tags[b*Sn + t - 1];
            partial += (e + T[tgp*NT + tg]) * mask[b*Sn + t];
        }
    }
    #pragma unroll
    for (int o = 16; o; o >>= 1) partial += __shfl_xor_sync(0xffffffffu, partial, o);
    if (lane == 0) g_score[b] = partial;
}

// ============================ loss reduction ============================
__global__ __launch_bounds__(32)
void loss_kernel(float* __restrict__ out)
{
    int l = threadIdx.x;
    float v = (g_partition[2*l]   - g_score[2*l])
            + (g_partition[2*l+1] - g_score[2*l+1]);
    #pragma unroll
    for (int o = 16; o; o >>= 1) v += __shfl_xor_sync(0xffffffffu, v, o);
    if (l == 0) out[0] = v;
}

// ============================ launch ============================
extern "C" void kernel_launch(void* const* d_in, const int* in_sizes, int n_in,
                              void* d_out, int out_size)
{
    const float* em   = (const float*)d_in[0];   // (B,S,D)
    const int*   tags = (const int*)  d_in[1];   // (B,S)
    const float* mask = (const float*)d_in[2];   // (B,S)
    const float* W    = (const float*)d_in[3];   // (D,N)
    const float* bias = (const float*)d_in[4];   // (N,)
    const float* T    = (const float*)d_in[5];   // (N,N)
    float* out = (float*)d_out;                  // [loss, logits(B,S,33)]

    gemm_kernel <<<(Bn*Sn)/ROWS_PER_BLK, GEMM_THREADS>>>(em, W, bias, out);
    scan_kernel <<<Bn, 64>>>(T, mask);
    score_kernel<<<Bn, 32>>>(tags, mask, T);
    loss_kernel <<<1, 32>>>(out);
}

// round 2
// speedup vs baseline: 1.2476x; 1.2476x over previous
#include <cuda_runtime.h>

#define Bn   64
#define Sn   1024
#define Dn   1024
#define NT   34      // tags incl BOS
#define NA   33      // active states (BOS column is -1e4 => dead state)
#define BOSI 33

// -------- scratch (static device allocations) --------
__device__ float  g_exp_proj[(size_t)Bn * NA * Sn];  // [b][j][t] exp(proj), transposed
__device__ double g_partition[Bn];
__device__ float  g_score[Bn];

// ============================ GEMM ============================
// proj = emissions @ W + b. Only 33 useful columns. Writes raw logits to out
// and exp(proj) transposed to g_exp_proj.
#define KT            32
#define GEMM_THREADS  128
#define ROWS_PER_BLK  256

#define GEMM_U(EA0, EA1, KK) do{                                          \
    const float4* wr_ = (const float4*)(&Wt[(KK)][0]);                    \
    _Pragma("unroll")                                                     \
    for (int j4 = 0; j4 < 8; j4++){                                       \
        float4 w_ = wr_[j4];                                              \
        acc0[j4*4+0] += (EA0)*w_.x; acc0[j4*4+1] += (EA0)*w_.y;           \
        acc0[j4*4+2] += (EA0)*w_.z; acc0[j4*4+3] += (EA0)*w_.w;           \
        acc1[j4*4+0] += (EA1)*w_.x; acc1[j4*4+1] += (EA1)*w_.y;           \
        acc1[j4*4+2] += (EA1)*w_.z; acc1[j4*4+3] += (EA1)*w_.w;           \
    }                                                                     \
    float wl_ = Wt[(KK)][32];                                             \
    acc0[32] += (EA0)*wl_;  acc1[32] += (EA1)*wl_;                        \
} while(0)

__global__ __launch_bounds__(GEMM_THREADS, 2)
void gemm_kernel(const float* __restrict__ em, const float* __restrict__ W,
                 const float* __restrict__ bias, float* __restrict__ out)
{
    __shared__ __align__(16) float Wt[KT][36];
    int tid  = threadIdx.x;
    int row0 = blockIdx.x * ROWS_PER_BLK + tid;
    int row1 = row0 + GEMM_THREADS;

    float acc0[NA], acc1[NA];
    #pragma unroll
    for (int j = 0; j < NA; j++){ acc0[j] = 0.f; acc1[j] = 0.f; }

    const float4* e0 = (const float4*)(em + (size_t)row0 * Dn);
    const float4* e1 = (const float4*)(em + (size_t)row1 * Dn);

    for (int k0 = 0; k0 < Dn; k0 += KT){
        __syncthreads();
        for (int i = tid; i < KT*NA; i += GEMM_THREADS){
            int kk = i / NA, j = i - kk*NA;
            Wt[kk][j] = W[(size_t)(k0 + kk)*NT + j];
        }
        __syncthreads();

        int kb4 = k0 >> 2;
        #pragma unroll
        for (int kk4 = 0; kk4 < KT/4; kk4++){
            float4 a0 = e0[kb4 + kk4];
            float4 a1 = e1[kb4 + kk4];
            const int kk = kk4*4;
            GEMM_U(a0.x, a1.x, kk+0);
            GEMM_U(a0.y, a1.y, kk+1);
            GEMM_U(a0.z, a1.z, kk+2);
            GEMM_U(a0.w, a1.w, kk+3);
        }
    }

    int b0 = row0 >> 10, s0 = row0 & 1023;
    int b1 = row1 >> 10, s1 = row1 & 1023;
    #pragma unroll
    for (int j = 0; j < NA; j++){
        float bj = bias[j];
        float v0 = acc0[j] + bj;
        float v1 = acc1[j] + bj;
        g_exp_proj[((size_t)b0*NA + j)*Sn + s0] = __expf(v0);
        g_exp_proj[((size_t)b1*NA + j)*Sn + s1] = __expf(v1);
        out[1 + (size_t)row0*NA + j] = v0;
        out[1 + (size_t)row1*NA + j] = v1;
    }
}

// ============================ CRF forward scan ============================
// Linear space: p_t[j] = (sum_i p_{t-1}[i] * E[i][j]) * exp(em_t[j]), rescaled
// every step by an exact power of two taken from the exponent bits of p[0]
// (identical in all threads - no extra exchange). One barrier per step.
// Transcendental-free inner loop. partition = cnt*ln2 + log(sum p_final).

#define CRF_STEP(RB, WB, EM, MK) do {                                      \
    float s_ = 0.f;                                                        \
    unsigned eb_;                                                          \
    {                                                                      \
        const float4* p4_ = (const float4*)pbuf[RB];                       \
        float4 q0 = p4_[0];                                                \
        eb_ = (__float_as_uint(q0.x) >> 23);                               \
        if (act) {                                                         \
            float mv0, mv1, mv2, mv3;                                      \
            mv0 = q0.x*Ereg[0]; mv1 = q0.y*Ereg[1];                        \
            mv2 = q0.z*Ereg[2]; mv3 = q0.w*Ereg[3];                        \
            _Pragma("unroll")                                              \
            for (int i4 = 1; i4 < 9; i4++){                                \
                float4 qv = p4_[i4];                                       \
                mv0 += qv.x*Ereg[i4*4+0];                                  \
                mv1 += qv.y*Ereg[i4*4+1];                                  \
                mv2 += qv.z*Ereg[i4*4+2];                                  \
                mv3 += qv.w*Ereg[i4*4+3];                                  \
            }                                                              \
            s_ = ((mv0+mv1) + (mv2+mv3)) * (EM);                           \
        }                                                                  \
    }                                                                      \
    cnt += (int)eb_ - 127;                                                 \
    float scale_ = __uint_as_float((254u - eb_) << 23);                    \
    if (act) {                                                             \
        float base_ = ((MK) != 0.f) ? s_ : p_old;                          \
        p_old = base_ * scale_;                                            \
        pbuf[WB][j] = p_old;                                               \
    }                                                                      \
    __syncthreads();                                                       \
} while(0)

__global__ __launch_bounds__(64)
void scan_kernel(const float* __restrict__ T, const float* __restrict__ mask)
{
    __shared__ __align__(16) float pbuf[2][40];

    int b = blockIdx.x;
    int j = threadIdx.x;
    bool act = (j < NA);

    float Ereg[36];
    if (act){
        #pragma unroll
        for (int i = 0; i < NA; i++) Ereg[i] = __expf(T[i*NT + j]);
        Ereg[33] = 0.f; Ereg[34] = 0.f; Ereg[35] = 0.f;
    } else {
        #pragma unroll
        for (int i = 0; i < 36; i++) Ereg[i] = 0.f;
    }
    // zero pads in both buffers (slots 33..39)
    if (j >= NA && j < 40){ pbuf[0][j] = 0.f; pbuf[1][j] = 0.f; }

    const float4* ep4 = (const float4*)(g_exp_proj + ((size_t)b*NA + (act ? j : 0)) * Sn);
    const float4* mp4 = (const float4*)(mask + (size_t)b * Sn);

    float4 emv = ep4[0];
    float4 mkv = mp4[0];

    float p_old = 0.f;
    int cnt = 0;
    if (act){
        p_old = __expf(T[BOSI*NT + j]) * emv.x;   // exp(alpha0[j])
        pbuf[0][j] = p_old;
    }
    __syncthreads();

    float4 emn = ep4[1];
    float4 mkn = mp4[1];

    // t = 1..3
    CRF_STEP(0, 1, emv.y, mkv.y);
    CRF_STEP(1, 0, emv.z, mkv.z);
    CRF_STEP(0, 1, emv.w, mkv.w);

    for (int g = 1; g < Sn/4; g++){
        emv = emn; mkv = mkn;
        if (g + 1 < Sn/4){ emn = ep4[g+1]; mkn = mp4[g+1]; }
        CRF_STEP(1, 0, emv.x, mkv.x);
        CRF_STEP(0, 1, emv.y, mkv.y);
        CRF_STEP(1, 0, emv.z, mkv.z);
        CRF_STEP(0, 1, emv.w, mkv.w);
    }

    // final alphas live in pbuf[1] (t=1023 is odd)
    if (j == 0){
        const float* pf = pbuf[1];
        float ssum = 0.f;
        #pragma unroll
        for (int i = 0; i < NA; i++) ssum += pf[i];
        g_partition[b] = (double)cnt * 0.6931471805599453 + log((double)ssum);
    }
}

// ============================ gold-path score ============================
__global__ __launch_bounds__(32)
void score_kernel(const int* __restrict__ tags, const float* __restrict__ mask,
                  const float* __restrict__ T, const float* __restrict__ out)
{
    int b = blockIdx.x, lane = threadIdx.x;
    float partial = 0.f;
    for (int t = lane; t < Sn; t += 32){
        int   tg = tags[b*Sn + t];
        float e  = out[1 + ((size_t)b*Sn + t)*NA + tg];   // raw logits
        if (t == 0){
            partial += T[BOSI*NT + tg] + e;
        } else {
            int tgp = tags[b*Sn + t - 1];
            partial += (e + T[tgp*NT + tg]) * mask[b*Sn + t];
        }
    }
    #pragma unroll
    for (int o = 16; o; o >>= 1) partial += __shfl_xor_sync(0xffffffffu, partial, o);
    if (lane == 0) g_score[b] = partial;
}

// ============================ loss reduction ============================
__global__ __launch_bounds__(32)
void loss_kernel(float* __restrict__ out)
{
    int l = threadIdx.x;
    double v = (g_partition[2*l]   - (double)g_score[2*l])
             + (g_partition[2*l+1] - (double)g_score[2*l+1]);
    #pragma unroll
    for (int o = 16; o; o >>= 1) v += __shfl_xor_sync(0xffffffffu, v, o);
    if (l == 0) out[0] = (float)v;
}

// ============================ launch ============================
extern "C" void kernel_launch(void* const* d_in, const int* in_sizes, int n_in,
                              void* d_out, int out_size)
{
    const float* em   = (const float*)d_in[0];   // (B,S,D)
    const int*   tags = (const int*)  d_in[1];   // (B,S)
    const float* mask = (const float*)d_in[2];   // (B,S)
    const float* W    = (const float*)d_in[3];   // (D,N)
    const float* bias = (const float*)d_in[4];   // (N,)
    const float* T    = (const float*)d_in[5];   // (N,N)
    float* out = (float*)d_out;                  // [loss, logits(B,S,33)]

    gemm_kernel <<<(Bn*Sn)/ROWS_PER_BLK, GEMM_THREADS>>>(em, W, bias, out);
    scan_kernel <<<Bn, 64>>>(T, mask);
    score_kernel<<<Bn, 32>>>(tags, mask, T, out);
    loss_kernel <<<1, 32>>>(out);
}

// round 8
// speedup vs baseline: 1.2783x; 1.0247x over previous
#include <cuda_runtime.h>
#include <cstdint>

#define Bn   64
#define Sn   1024
#define Dn   1024
#define NT   34      // tags incl BOS
#define NA   33      // active states (BOS column dead)
#define BOSI 33

// -------- scratch (static device allocations) --------
__device__ float  g_exp_proj[(size_t)Bn * NA * Sn];  // [b][j][t] exp(proj), transposed
__device__ double g_partition[Bn];
__device__ float  g_score[Bn];

// ============================ f32x2 helpers ============================
typedef unsigned long long u64;

__device__ __forceinline__ void ffma2(u64& d, u64 a, u64 b){
    asm("fma.rn.f32x2 %0, %1, %2, %0;" : "+l"(d) : "l"(a), "l"(b));
}
__device__ __forceinline__ u64 mul2(u64 a, u64 b){
    u64 r; asm("mul.rn.f32x2 %0, %1, %2;" : "=l"(r) : "l"(a), "l"(b)); return r;
}
__device__ __forceinline__ u64 add2(u64 a, u64 b){
    u64 r; asm("add.rn.f32x2 %0, %1, %2;" : "=l"(r) : "l"(a), "l"(b)); return r;
}
__device__ __forceinline__ u64 pack2(float x){           // {x, x}
    u64 r; asm("mov.b64 %0, {%1, %1};" : "=l"(r) : "f"(x)); return r;
}
__device__ __forceinline__ u64 packf2(float lo, float hi){
    u64 r; asm("mov.b64 %0, {%1, %2};" : "=l"(r) : "f"(lo), "f"(hi)); return r;
}
__device__ __forceinline__ void unpack2(u64 v, float& lo, float& hi){
    asm("mov.b64 {%0, %1}, %2;" : "=f"(lo), "=f"(hi) : "l"(v));
}

// ============================ GEMM ============================
// proj = emissions @ W + b, on packed f32x2 FMAs.
// 128 threads, 2 rows/thread, 256 rows/CTA, 256 CTAs. W tile staged in smem
// as 17 column-pairs per k (cols 0..33; col 33 computed but ignored).
#define KT            32
#define GEMM_THREADS  128
#define ROWS_PER_BLK  256

#define GU(A0, A1, KK) do{                                                \
    u64 pa0 = pack2(A0), pa1 = pack2(A1);                                 \
    const ulonglong2* wr_ = (const ulonglong2*)(&Wt[(KK)][0]);            \
    _Pragma("unroll")                                                     \
    for (int q = 0; q < 8; q++){                                          \
        ulonglong2 w_ = wr_[q];                                           \
        ffma2(acc0[2*q],   pa0, w_.x); ffma2(acc0[2*q+1], pa0, w_.y);     \
        ffma2(acc1[2*q],   pa1, w_.x); ffma2(acc1[2*q+1], pa1, w_.y);     \
    }                                                                     \
    u64 wl_ = Wt[(KK)][16];                                               \
    ffma2(acc0[16], pa0, wl_); ffma2(acc1[16], pa1, wl_);                 \
} while(0)

__global__ __launch_bounds__(GEMM_THREADS, 2)
void gemm_kernel(const float* __restrict__ em, const float* __restrict__ W,
                 const float* __restrict__ bias, float* __restrict__ out)
{
    __shared__ __align__(16) u64 Wt[KT][18];   // 17 used, stride 18 (144B, 16B-aligned)
    __shared__ float s_bias[NA];

    int tid  = threadIdx.x;
    int row0 = blockIdx.x * ROWS_PER_BLK + tid;
    int row1 = row0 + GEMM_THREADS;

    if (tid < NA) s_bias[tid] = bias[tid];

    u64 acc0[17], acc1[17];
    #pragma unroll
    for (int j = 0; j < 17; j++){ acc0[j] = 0ull; acc1[j] = 0ull; }

    const float4* e0 = (const float4*)(em + (size_t)row0 * Dn);
    const float4* e1 = (const float4*)(em + (size_t)row1 * Dn);

    for (int k0 = 0; k0 < Dn; k0 += KT){
        __syncthreads();
        for (int i = tid; i < KT*17; i += GEMM_THREADS){
            int kk = i / 17, j2 = i - kk*17;
            const float* wr = W + (size_t)(k0 + kk) * NT + 2*j2;
            Wt[kk][j2] = packf2(wr[0], wr[1]);   // 2*16+1 = 33 < 34: always in-bounds
        }
        __syncthreads();

        int kb4 = k0 >> 2;
        #pragma unroll
        for (int kk4 = 0; kk4 < KT/4; kk4++){
            float4 a0 = e0[kb4 + kk4];
            float4 a1 = e1[kb4 + kk4];
            const int kk = kk4*4;
            GU(a0.x, a1.x, kk+0);
            GU(a0.y, a1.y, kk+1);
            GU(a0.z, a1.z, kk+2);
            GU(a0.w, a1.w, kk+3);
        }
    }

    int b0 = row0 >> 10, s0 = row0 & 1023;
    int b1 = row1 >> 10, s1 = row1 & 1023;
    float* op0 = out + 1 + (size_t)row0 * NA;
    float* op1 = out + 1 + (size_t)row1 * NA;
    #pragma unroll
    for (int j2 = 0; j2 < 17; j2++){
        float lo0, hi0, lo1, hi1;
        unpack2(acc0[j2], lo0, hi0);
        unpack2(acc1[j2], lo1, hi1);
        int jl = 2*j2, jh = 2*j2 + 1;
        {
            float v0 = lo0 + s_bias[jl];
            float v1 = lo1 + s_bias[jl];
            op0[jl] = v0;  op1[jl] = v1;
            g_exp_proj[((size_t)b0*NA + jl)*Sn + s0] = __expf(v0);
            g_exp_proj[((size_t)b1*NA + jl)*Sn + s1] = __expf(v1);
        }
        if (jh < NA){
            float v0 = hi0 + s_bias[jh];
            float v1 = hi1 + s_bias[jh];
            op0[jh] = v0;  op1[jh] = v1;
            g_exp_proj[((size_t)b0*NA + jh)*Sn + s0] = __expf(v0);
            g_exp_proj[((size_t)b1*NA + jh)*Sn + s1] = __expf(v1);
        }
    }
}

// ============================ CRF forward scan ============================
// Linear space, power-of-two rescale from exponent bits of p[0]; matvec on
// f32x2 packed pairs (18 FFMA2 instead of 36 FFMA). One barrier per step.

#define CRF_STEP(RB, WB, EM, MK) do {                                      \
    float s_ = 0.f;                                                        \
    unsigned eb_;                                                          \
    {                                                                      \
        const ulonglong2* p2_ = (const ulonglong2*)pbuf[RB];               \
        ulonglong2 q0 = p2_[0];                                            \
        eb_ = ((unsigned)q0.x) >> 23;                                      \
        if (act) {                                                         \
            u64 m0 = mul2(q0.x, E2[0]);                                    \
            u64 m1 = mul2(q0.y, E2[1]);                                    \
            _Pragma("unroll")                                              \
            for (int q = 1; q < 8; q++){                                   \
                ulonglong2 qv = p2_[q];                                    \
                ffma2(m0, qv.x, E2[2*q]);                                  \
                ffma2(m1, qv.y, E2[2*q+1]);                                \
            }                                                              \
            u64 ql = ((const u64*)pbuf[RB])[16];                           \
            ffma2(m0, ql, E2[16]);                                         \
            m0 = add2(m0, m1);                                             \
            float lo_, hi_; unpack2(m0, lo_, hi_);                         \
            s_ = (lo_ + hi_) * (EM);                                       \
        }                                                                  \
    }                                                                      \
    cnt += (int)eb_ - 127;                                                 \
    float scale_ = __uint_as_float((254u - eb_) << 23);                    \
    if (act) {                                                             \
        float base_ = ((MK) != 0.f) ? s_ : p_old;                          \
        p_old = base_ * scale_;                                            \
        pbuf[WB][j] = p_old;                                               \
    }                                                                      \
    __syncthreads();                                                       \
} while(0)

__global__ __launch_bounds__(64)
void scan_kernel(const float* __restrict__ T, const float* __restrict__ mask)
{
    __shared__ __align__(16) float pbuf[2][40];

    int b = blockIdx.x;
    int j = threadIdx.x;
    bool act = (j < NA);

    u64 E2[17];
    if (act){
        #pragma unroll
        for (int i = 0; i < 16; i++)
            E2[i] = packf2(__expf(T[(2*i)*NT + j]), __expf(T[(2*i+1)*NT + j]));
        E2[16] = packf2(__expf(T[32*NT + j]), 0.f);   // pair (32, dead 33)
    } else {
        #pragma unroll
        for (int i = 0; i < 17; i++) E2[i] = 0ull;
    }
    if (j >= NA && j < 40){ pbuf[0][j] = 0.f; pbuf[1][j] = 0.f; }

    const float4* ep4 = (const float4*)(g_exp_proj + ((size_t)b*NA + (act ? j : 0)) * Sn);
    const float4* mp4 = (const float4*)(mask + (size_t)b * Sn);

    float4 emv = ep4[0];
    float4 mkv = mp4[0];

    float p_old = 0.f;
    int cnt = 0;
    if (act){
        p_old = __expf(T[BOSI*NT + j]) * emv.x;   // exp(alpha0[j])
        pbuf[0][j] = p_old;
    }
    __syncthreads();

    float4 emn = ep4[1];
    float4 mkn = mp4[1];

    CRF_STEP(0, 1, emv.y, mkv.y);
    CRF_STEP(1, 0, emv.z, mkv.z);
    CRF_STEP(0, 1, emv.w, mkv.w);

    for (int g = 1; g < Sn/4; g++){
        emv = emn; mkv = mkn;
        if (g + 1 < Sn/4){ emn = ep4[g+1]; mkn = mp4[g+1]; }
        CRF_STEP(1, 0, emv.x, mkv.x);
        CRF_STEP(0, 1, emv.y, mkv.y);
        CRF_STEP(1, 0, emv.z, mkv.z);
        CRF_STEP(0, 1, emv.w, mkv.w);
    }

    // final alphas live in pbuf[1] (t=1023 is odd)
    if (j == 0){
        const float* pf = pbuf[1];
        float ssum = 0.f;
        #pragma unroll
        for (int i = 0; i < NA; i++) ssum += pf[i];
        g_partition[b] = (double)cnt * 0.6931471805599453 + log((double)ssum);
    }
}

// ============================ gold-path score ============================
__global__ __launch_bounds__(32)
void score_kernel(const int* __restrict__ tags, const float* __restrict__ mask,
                  const float* __restrict__ T, const float* __restrict__ out)
{
    int b = blockIdx.x, lane = threadIdx.x;
    float partial = 0.f;
    for (int t = lane; t < Sn; t += 32){
        int   tg = tags[b*Sn + t];
        float e  = out[1 + ((size_t)b*Sn + t)*NA + tg];
        if (t == 0){
            partial += T[BOSI*NT + tg] + e;
        } else {
            int tgp = tags[b*Sn + t - 1];
            partial += (e + T[tgp*NT + tg]) * mask[b*Sn + t];
        }
    }
    #pragma unroll
    for (int o = 16; o; o >>= 1) partial += __shfl_xor_sync(0xffffffffu, partial, o);
    if (lane == 0) g_score[b] = partial;
}

// ============================ loss reduction ============================
__global__ __launch_bounds__(32)
void loss_kernel(float* __restrict__ out)
{
    int l = threadIdx.x;
    double v = (g_partition[2*l]   - (double)g_score[2*l])
             + (g_partition[2*l+1] - (double)g_score[2*l+1]);
    #pragma unroll
    for (int o = 16; o; o >>= 1) v += __shfl_xor_sync(0xffffffffu, v, o);
    if (l == 0) out[0] = (float)v;
}

// ============================ launch ============================
extern "C" void kernel_launch(void* const* d_in, const int* in_sizes, int n_in,
                              void* d_out, int out_size)
{
    const float* em   = (const float*)d_in[0];   // (B,S,D)
    const int*   tags = (const int*)  d_in[1];   // (B,S)
    const float* mask = (const float*)d_in[2];   // (B,S)
    const float* W    = (const float*)d_in[3];   // (D,N)
    const float* bias = (const float*)d_in[4];   // (N,)
    const float* T    = (const float*)d_in[5];   // (N,N)
    float* out = (float*)d_out;                  // [loss, logits(B,S,33)]

    gemm_kernel <<<(Bn*Sn)/ROWS_PER_BLK, GEMM_THREADS>>>(em, W, bias, out);
    scan_kernel <<<Bn, 64>>>(T, mask);
    score_kernel<<<Bn, 32>>>(tags, mask, T, out);
    loss_kernel <<<1, 32>>>(out);
}

// round 9
// speedup vs baseline: 1.3955x; 1.0917x over previous
#include <cuda_runtime.h>
#include <cstdint>

#define Bn   64
#define Sn   1024
#define Dn   1024
#define NT   34      // tags incl BOS
#define NA   33      // active states (BOS column dead)
#define BOSI 33
#define NP   40      // padded N for mma (5 x n8)

// -------- scratch (static device allocations) --------
__device__ float  g_exp_proj[(size_t)Bn * NA * Sn];  // [b][j][t] exp(proj)
__device__ float  g_Wh[Dn * NP];                     // W hi (tf32 bits as f32), [k][40]
__device__ float  g_Wl[Dn * NP];                     // W lo
__device__ float  g_pm[Bn][NA];                      // forward p at mid
__device__ float  g_vm[Bn][NA];                      // backward v at mid
__device__ int    g_cntf[Bn], g_cntb[Bn];
__device__ float  g_score[Bn];

__device__ __forceinline__ uint32_t tf32_hi(float x){
    uint32_t u; asm("cvt.rna.tf32.f32 %0, %1;" : "=r"(u) : "f"(x)); return u;
}

// ============================ prep: split W into tf32 hi/lo, padded ============================
__global__ __launch_bounds__(1024)
void prep_kernel(const float* __restrict__ W)
{
    int idx = blockIdx.x * 1024 + threadIdx.x;   // 40960 = 1024 k x 40 n
    int k = idx / NP, n = idx - k * NP;
    float w = (n < NA) ? W[(size_t)k * NT + n] : 0.f;
    uint32_t hi = tf32_hi(w);
    float lo = w - __uint_as_float(hi);
    g_Wh[idx] = __uint_as_float(hi);
    g_Wl[idx] = __uint_as_float(tf32_hi(lo));
}

// ============================ GEMM: mma.sync m16n8k8 tf32, 3-term split ============================
// 512 CTAs x 128 thr (4 warps). CTA: 128 rows. Warp: 32 rows (2 m16 tiles). N=40 (5 n8).
#define KC 16

__device__ __forceinline__ void mma_tf32(float* d, const uint32_t* a, uint32_t b0, uint32_t b1){
    asm volatile("mma.sync.aligned.m16n8k8.row.col.f32.tf32.tf32.f32 "
        "{%0,%1,%2,%3}, {%4,%5,%6,%7}, {%8,%9}, {%0,%1,%2,%3};"
        : "+f"(d[0]), "+f"(d[1]), "+f"(d[2]), "+f"(d[3])
        : "r"(a[0]), "r"(a[1]), "r"(a[2]), "r"(a[3]), "r"(b0), "r"(b1));
}

__global__ __launch_bounds__(128, 4)
void gemm_kernel(const float* __restrict__ em, const float* __restrict__ bias,
                 float* __restrict__ out)
{
    __shared__ __align__(16) float As[128][20];       // stride 20: 16B-aligned rows, conflict-free frags
    __shared__ __align__(16) float Whs[KC][NP];
    __shared__ __align__(16) float Wls[KC][NP];
    __shared__ float s_bias[NP];

    const int tid = threadIdx.x;
    const int wid = tid >> 5;
    const int lane = tid & 31;
    const int g  = lane >> 2;       // group id (row within tile)
    const int t4 = lane & 3;        // thread in group (k col)
    const int row_base = blockIdx.x * 128;

    if (tid < NP) s_bias[tid] = (tid < NA) ? bias[tid] : 0.f;

    float acc[2][5][4];
    #pragma unroll
    for (int mt = 0; mt < 2; mt++)
        #pragma unroll
        for (int nt = 0; nt < 5; nt++)
            #pragma unroll
            for (int q = 0; q < 4; q++) acc[mt][nt][q] = 0.f;

    for (int kt = 0; kt < Dn / KC; kt++){
        const int k0 = kt * KC;
        __syncthreads();
        {   // stage A: thread t loads row t, cols k0..k0+15 (4 float4)
            const float4* src = (const float4*)(em + (size_t)(row_base + tid) * Dn + k0);
            float4* dst = (float4*)(&As[tid][0]);
            #pragma unroll
            for (int q = 0; q < 4; q++) dst[q] = src[q];
            // stage W hi/lo: 160 float4 each
            const float4* wh = (const float4*)(g_Wh + k0 * NP);
            const float4* wl = (const float4*)(g_Wl + k0 * NP);
            float4* dh = (float4*)(&Whs[0][0]);
            float4* dl = (float4*)(&Wls[0][0]);
            #pragma unroll
            for (int i4 = tid; i4 < (KC * NP) / 4; i4 += 128){ dh[i4] = wh[i4]; dl[i4] = wl[i4]; }
        }
        __syncthreads();

        #pragma unroll
        for (int ks = 0; ks < 2; ks++){
            const int k8 = ks * 8;
            // B fragments (5 n-tiles, hi & lo)
            uint32_t bh0[5], bh1[5], bl0[5], bl1[5];
            #pragma unroll
            for (int nt = 0; nt < 5; nt++){
                int n = nt * 8 + g;
                bh0[nt] = __float_as_uint(Whs[k8 + t4][n]);
                bh1[nt] = __float_as_uint(Whs[k8 + t4 + 4][n]);
                bl0[nt] = __float_as_uint(Wls[k8 + t4][n]);
                bl1[nt] = __float_as_uint(Wls[k8 + t4 + 4][n]);
            }
            // A fragments (2 m-tiles), split hi/lo on the fly
            uint32_t ah[2][4], al[2][4];
            #pragma unroll
            for (int mt = 0; mt < 2; mt++){
                int r = wid * 32 + mt * 16 + g;
                float f0 = As[r][k8 + t4];
                float f1 = As[r + 8][k8 + t4];
                float f2 = As[r][k8 + t4 + 4];
                float f3 = As[r + 8][k8 + t4 + 4];
                ah[mt][0] = tf32_hi(f0); al[mt][0] = tf32_hi(f0 - __uint_as_float(ah[mt][0]));
                ah[mt][1] = tf32_hi(f1); al[mt][1] = tf32_hi(f1 - __uint_as_float(ah[mt][1]));
                ah[mt][2] = tf32_hi(f2); al[mt][2] = tf32_hi(f2 - __uint_as_float(ah[mt][2]));
                ah[mt][3] = tf32_hi(f3); al[mt][3] = tf32_hi(f3 - __uint_as_float(ah[mt][3]));
            }
            #pragma unroll
            for (int mt = 0; mt < 2; mt++)
                #pragma unroll
                for (int nt = 0; nt < 5; nt++){
                    mma_tf32(acc[mt][nt], ah[mt], bh0[nt], bh1[nt]);
                    mma_tf32(acc[mt][nt], ah[mt], bl0[nt], bl1[nt]);
                    mma_tf32(acc[mt][nt], al[mt], bh0[nt], bh1[nt]);
                }
        }
    }

    // epilogue: d0:(g, 2t), d1:(g, 2t+1), d2:(g+8, 2t), d3:(g+8, 2t+1)
    #pragma unroll
    for (int mt = 0; mt < 2; mt++){
        int r0 = row_base + wid * 32 + mt * 16 + g;
        int r1 = r0 + 8;
        #pragma unroll
        for (int nt = 0; nt < 5; nt++){
            int c0 = nt * 8 + 2 * t4;
            int c1 = c0 + 1;
            float v00 = acc[mt][nt][0] + s_bias[c0];
            float v01 = acc[mt][nt][1] + s_bias[c1];
            float v10 = acc[mt][nt][2] + s_bias[c0];
            float v11 = acc[mt][nt][3] + s_bias[c1];
            int b0 = r0 >> 10, s0 = r0 & 1023;
            int b1 = r1 >> 10, s1 = r1 & 1023;
            if (c0 < NA){
                out[1 + (size_t)r0 * NA + c0] = v00;
                out[1 + (size_t)r1 * NA + c0] = v10;
                g_exp_proj[((size_t)b0 * NA + c0) * Sn + s0] = __expf(v00);
                g_exp_proj[((size_t)b1 * NA + c0) * Sn + s1] = __expf(v10);
            }
            if (c1 < NA){
                out[1 + (size_t)r0 * NA + c1] = v01;
                out[1 + (size_t)r1 * NA + c1] = v11;
                g_exp_proj[((size_t)b0 * NA + c1) * Sn + s0] = __expf(v01);
                g_exp_proj[((size_t)b1 * NA + c1) * Sn + s1] = __expf(v11);
            }
        }
    }
}

// ============================ CRF scan: fwd/bwd split, single-warp shuffle ============================
// grid 128 x 32: block (2b+dir). Lane j owns state j; state 32 replicated in all lanes
// (its E-column/row and em stream are lane-uniform). Linear space, power-of-2 rescale
// from exponent of state-0 value each step. No barriers, no smem.

#define SCAN_BODY(PL, PH, EMJ, EM32, MK, DOT_W)                                \
{                                                                              \
    float p0v = __shfl_sync(0xffffffffu, PL, 0);                               \
    unsigned eb = __float_as_uint(p0v) >> 23;                                  \
    cnt += (int)eb - 127;                                                      \
    float scl = __uint_as_float((254u - eb) << 23);                            \
    float al0=0.f, al1=0.f, al2=0.f, al3=0.f;                                  \
    float ahh0=0.f, ahh1=0.f, ahh2=0.f, ahh3=0.f;                              \
    float wl = (DOT_W) ? (PL) * (EMJ)  : (PL);                                 \
    float wh = (DOT_W) ? (PH) * (EM32) : (PH);                                 \
    _Pragma("unroll")                                                          \
    for (int i = 0; i < 32; i += 4){                                           \
        float v0 = __shfl_sync(0xffffffffu, wl, i);                            \
        float v1 = __shfl_sync(0xffffffffu, wl, i+1);                          \
        float v2 = __shfl_sync(0xffffffffu, wl, i+2);                          \
        float v3 = __shfl_sync(0xffffffffu, wl, i+3);                          \
        al0 += v0*E_l[i];   ahh0 += v0*E_h[i];                                 \
        al1 += v1*E_l[i+1]; ahh1 += v1*E_h[i+1];                               \
        al2 += v2*E_l[i+2]; ahh2 += v2*E_h[i+2];                               \
        al3 += v3*E_l[i+3]; ahh3 += v3*E_h[i+3];                               \
    }                                                                          \
    al0 += wh*E_l[32]; ahh0 += wh*E_h[32];                                     \
    float sl = (al0+al1)+(al2+al3);                                            \
    float sh = (ahh0+ahh1)+(ahh2+ahh3);                                        \
    float nl, nh;                                                              \
    if (DOT_W){ nl = sl*scl; nh = sh*scl; }                                    \
    else      { nl = sl*((EMJ)*scl); nh = sh*((EM32)*scl); }                   \
    if ((MK) == 0.f){ nl = (PL)*scl; nh = (PH)*scl; }                          \
    PL = nl; PH = nh;                                                          \
}

__global__ __launch_bounds__(32)
void scan_kernel(const float* __restrict__ T, const float* __restrict__ mask)
{
    const int b   = blockIdx.x >> 1;
    const int dir = blockIdx.x & 1;
    const int j   = threadIdx.x;

    float E_l[NA], E_h[NA];
    if (dir == 0){
        // forward: E_l[i] = exp(T[i][j]), E_h[i] = exp(T[i][32])
        #pragma unroll
        for (int i = 0; i < NA; i++){
            E_l[i] = __expf(T[i*NT + j]);
            E_h[i] = __expf(T[i*NT + 32]);
        }
    } else {
        // backward: E_l[s] = exp(T[j][s]), E_h[s] = exp(T[32][s])
        #pragma unroll
        for (int s = 0; s < NA; s++){
            E_l[s] = __expf(T[j*NT + s]);
            E_h[s] = __expf(T[32*NT + s]);
        }
    }

    const float4* epj  = (const float4*)(g_exp_proj + ((size_t)b*NA + j ) * Sn);
    const float4* ep32 = (const float4*)(g_exp_proj + ((size_t)b*NA + 32) * Sn);
    const float4* mp4  = (const float4*)(mask + (size_t)b * Sn);

    int cnt = 0;

    if (dir == 0){
        // ---- forward: t = 1..511 ----
        float4 e = epj[0], e32 = ep32[0], mk = mp4[0];
        float pl = __expf(T[BOSI*NT + j])  * e.x;
        float ph = __expf(T[BOSI*NT + 32]) * e32.x;

        SCAN_BODY(pl, ph, e.y, e32.y, mk.y, 0);
        SCAN_BODY(pl, ph, e.z, e32.z, mk.z, 0);
        SCAN_BODY(pl, ph, e.w, e32.w, mk.w, 0);
        for (int gq = 1; gq < 128; gq++){
            e = epj[gq]; e32 = ep32[gq]; mk = mp4[gq];
            SCAN_BODY(pl, ph, e.x, e32.x, mk.x, 0);
            SCAN_BODY(pl, ph, e.y, e32.y, mk.y, 0);
            SCAN_BODY(pl, ph, e.z, e32.z, mk.z, 0);
            SCAN_BODY(pl, ph, e.w, e32.w, mk.w, 0);
        }
        g_pm[b][j] = pl;
        if (j == 0){ g_pm[b][32] = ph; g_cntf[b] = cnt; }
    } else {
        // ---- backward: t = 1023 down to 512 ----
        float vl = 1.f, vh = 1.f;
        for (int gq = 255; gq >= 128; gq--){
            float4 e = epj[gq], e32 = ep32[gq], mk = mp4[gq];
            SCAN_BODY(vl, vh, e.w, e32.w, mk.w, 1);
            SCAN_BODY(vl, vh, e.z, e32.z, mk.z, 1);
            SCAN_BODY(vl, vh, e.y, e32.y, mk.y, 1);
            SCAN_BODY(vl, vh, e.x, e32.x, mk.x, 1);
        }
        g_vm[b][j] = vl;
        if (j == 0){ g_vm[b][32] = vh; g_cntb[b] = cnt; }
    }
}

// ============================ gold-path score ============================
__global__ __launch_bounds__(32)
void score_kernel(const int* __restrict__ tags, const float* __restrict__ mask,
                  const float* __restrict__ T, const float* __restrict__ out)
{
    int b = blockIdx.x, lane = threadIdx.x;
    float partial = 0.f;
    for (int t = lane; t < Sn; t += 32){
        int   tg = tags[b*Sn + t];
        float e  = out[1 + ((size_t)b*Sn + t)*NA + tg];
        if (t == 0){
            partial += T[BOSI*NT + tg] + e;
        } else {
            int tgp = tags[b*Sn + t - 1];
            partial += (e + T[tgp*NT + tg]) * mask[b*Sn + t];
        }
    }
    #pragma unroll
    for (int o = 16; o; o >>= 1) partial += __shfl_xor_sync(0xffffffffu, partial, o);
    if (lane == 0) g_score[b] = partial;
}

// ============================ combine + loss ============================
__global__ __launch_bounds__(64)
void loss_kernel(float* __restrict__ out)
{
    __shared__ double red[64];
    int b = threadIdx.x;
    double dot = 0.0;
    #pragma unroll
    for (int i = 0; i < NA; i++) dot += (double)g_pm[b][i] * (double)g_vm[b][i];
    double part = (double)(g_cntf[b] + g_cntb[b]) * 0.6931471805599453 + log(dot);
    red[b] = part - (double)g_score[b];
    __syncthreads();
    if (b == 0){
        double s = 0.0;
        #pragma unroll
        for (int i = 0; i < 64; i++) s += red[i];
        out[0] = (float)s;
    }
}

// ============================ launch ============================
extern "C" void kernel_launch(void* const* d_in, const int* in_sizes, int n_in,
                              void* d_out, int out_size)
{
    const float* em   = (const float*)d_in[0];   // (B,S,D)
    const int*   tags = (const int*)  d_in[1];   // (B,S)
    const float* mask = (const float*)d_in[2];   // (B,S)
    const float* W    = (const float*)d_in[3];   // (D,N)
    const float* bias = (const float*)d_in[4];   // (N,)
    const float* T    = (const float*)d_in[5];   // (N,N)
    float* out = (float*)d_out;                  // [loss, logits(B,S,33)]

    prep_kernel <<<(Dn*NP)/1024, 1024>>>(W);
    gemm_kernel <<<(Bn*Sn)/128, 128>>>(em, bias, out);
    scan_kernel <<<2*Bn, 32>>>(T, mask);
    score_kernel<<<Bn, 32>>>(tags, mask, T, out);
    loss_kernel <<<1, 64>>>(out);
}